// round 10
// baseline (speedup 1.0000x reference)
#include <cuda_runtime.h>
#include <math.h>

#define DD    512
#define HH    256
#define G4    1024
#define NT    128
#define NB    5
#define NEP   1024
#define M640  640      // NT*NB
#define CLN   8        // cluster size (CTAs per direction)

// scan smem layout (floats)
#define WPITCH   132
#define OFF_W    0                       // wT[256][132]  (transposed w_hh slice)
#define OFF_H    33792                   // hsm[2][NB][256]
#define RPITCH   132
#define OFF_RED  36352                   // red[16*NB][132]
#define OFF_GARR 46912                   // garr[640]
#define SMEM_SCAN_FLOATS 47552
#define SMEM_SCAN_BYTES  (SMEM_SCAN_FLOATS * 4)

// ---------- static device scratch (no allocation) ----------
__device__ __align__(16) float g_v[DD];
__device__ float g_c0;
__device__ __align__(16) float g_scores[NEP];
__device__ int   g_idx[8];
__device__ float g_wsel[8];
__device__ __align__(16) float g_x0 [M640 * DD];
__device__ __align__(16) float g_x1 [M640 * DD];
__device__ __align__(16) float g_lout[M640 * DD];
__device__ __align__(16) float g_pre[2 * M640 * G4];

// ---------- helpers ----------
union F2U { float2 f; unsigned long long u; };
__device__ __forceinline__ float2 f2fma(float2 a, float2 b, float2 c) {
    F2U A, B, C, Dv; A.f = a; B.f = b; C.f = c;
    asm("fma.rn.f32x2 %0, %1, %2, %3;" : "=l"(Dv.u) : "l"(A.u), "l"(B.u), "l"(C.u));
    return Dv.f;
}
__device__ __forceinline__ float fast_tanh(float x) {
    float r; asm("tanh.approx.f32 %0, %1;" : "=f"(r) : "f"(x)); return r;
}
__device__ __forceinline__ float fast_sigmoid(float x) {
    return __fdividef(1.f, 1.f + __expf(-x));
}
__device__ __forceinline__ unsigned smem_u32(const void* p) {
    return (unsigned)__cvta_generic_to_shared(p);
}
__device__ __forceinline__ void mbar_init(unsigned a, unsigned cnt) {
    asm volatile("mbarrier.init.shared.b64 [%0], %1;" :: "r"(a), "r"(cnt) : "memory");
}
__device__ __forceinline__ void cluster_sync_() {
    asm volatile("barrier.cluster.arrive.aligned;" ::: "memory");
    asm volatile("barrier.cluster.wait.aligned;" ::: "memory");
}
__device__ __forceinline__ void st_cluster(unsigned laddr, unsigned rank, float v) {
    asm volatile("{\n\t.reg .b32 ra;\n\t"
                 "mapa.shared::cluster.u32 ra, %0, %1;\n\t"
                 "st.shared::cluster.f32 [ra], %2;\n\t}"
                 :: "r"(laddr), "r"(rank), "f"(v) : "memory");
}
__device__ __forceinline__ void arrive_cluster(unsigned mbar, unsigned rank) {
    asm volatile("{\n\t.reg .b32 ra;\n\t"
                 "mapa.shared::cluster.u32 ra, %0, %1;\n\t"
                 "mbarrier.arrive.release.cluster.shared::cluster.b64 _, [ra];\n\t}"
                 :: "r"(mbar), "r"(rank) : "memory");
}
__device__ __forceinline__ void wait_parity_cluster(unsigned mbar, unsigned parity) {
    asm volatile(
        "{\n\t.reg .pred P;\n"
        "LAB_%=:\n\t"
        "mbarrier.try_wait.parity.acquire.cluster.shared::cta.b64 P, [%0], %1, 0x989680;\n\t"
        "@P bra.uni DONE_%=;\n\t"
        "bra.uni LAB_%=;\n"
        "DONE_%=:\n\t}"
        :: "r"(mbar), "r"(parity) : "memory");
}

// ---------------- qp = Wq@q + bq ; v = Wk^T@qp ; c0 = bk.qp ----------------
__global__ void k_prep(const float* __restrict__ query, const float* __restrict__ Wq,
                       const float* __restrict__ bq, const float* __restrict__ Wk,
                       const float* __restrict__ bk) {
    __shared__ float qs[DD], qps[DD], red[DD];
    int tid = threadIdx.x;
    qs[tid] = query[tid];
    __syncthreads();
    const float* wr = Wq + (size_t)tid * DD;
    float s = bq[tid];
#pragma unroll 8
    for (int d = 0; d < DD; d++) s += wr[d] * qs[d];
    qps[tid] = s;
    __syncthreads();
    float vv = 0.f;
#pragma unroll 8
    for (int e = 0; e < DD; e++) vv += Wk[(size_t)e * DD + tid] * qps[e];
    g_v[tid] = vv;
    red[tid] = bk[tid] * qps[tid];
    __syncthreads();
    for (int st = 256; st > 0; st >>= 1) {
        if (tid < st) red[tid] += red[tid + st];
        __syncthreads();
    }
    if (tid == 0) g_c0 = red[0];
}

// ---------------- scores[n] = mean_l(ep[n][l]) . v + c0 ----------------
__global__ void k_scores(const float* __restrict__ ep) {
    __shared__ float4 vs[DD / 4];
    __shared__ float sred[256];
    int tid = threadIdx.x;
    if (tid < 128) vs[tid] = ((const float4*)g_v)[tid];
    __syncthreads();
    const float4* e4 = (const float4*)ep + (size_t)blockIdx.x * (NT * DD / 4);
    float acc = 0.f;
#pragma unroll 4
    for (int it = 0; it < 64; it++) {
        int i = tid + 256 * it;
        float4 x = e4[i];
        float4 w = vs[i & 127];
        acc += x.x * w.x + x.y * w.y + x.z * w.z + x.w * w.w;
    }
    sred[tid] = acc;
    __syncthreads();
    for (int st = 128; st > 0; st >>= 1) {
        if (tid < st) sred[tid] += sred[tid + st];
        __syncthreads();
    }
    if (tid == 0) g_scores[blockIdx.x] = sred[0] * (1.0f / NT) + g_c0;
}

// ---------------- iterative top-5 ----------------
__global__ void __launch_bounds__(1024) k_topk(const float* __restrict__ ages) {
    __shared__ float sc[NEP];
    __shared__ float rv[1024];
    __shared__ int   ri[1024];
    int tid = threadIdx.x;
    sc[tid] = g_scores[tid];
    __syncthreads();
    for (int r = 0; r < NB; r++) {
        rv[tid] = sc[tid]; ri[tid] = tid;
        __syncthreads();
        for (int st = 512; st > 0; st >>= 1) {
            if (tid < st) {
                float ov = rv[tid + st]; int oi = ri[tid + st];
                if (ov > rv[tid] || (ov == rv[tid] && oi < ri[tid])) { rv[tid] = ov; ri[tid] = oi; }
            }
            __syncthreads();
        }
        if (tid == 0) {
            g_idx[r]  = ri[0];
            g_wsel[r] = 1.f / (1.f + ages[ri[0]] * 0.01f);
            sc[ri[0]] = -INFINITY;
        }
        __syncthreads();
    }
}

// ---------------- x0[t][b][d] = ep[idx[b]][t][d] * w[b] ----------------
__global__ void k_gather(const float* __restrict__ ep) {
    int t = blockIdx.x, b = blockIdx.y, tid = threadIdx.x;
    int n = g_idx[b];
    float wv = g_wsel[b];
    const float4* src = (const float4*)(ep + ((size_t)n * NT + t) * DD);
    float4* dst = (float4*)(g_x0 + ((size_t)t * NB + b) * DD);
    float4 x = src[tid];
    x.x *= wv; x.y *= wv; x.z *= wv; x.w *= wv;
    dst[tid] = x;
}

// ---------------- pre-gate GEMM: pre[dir][m][j] = X[m].Wih[j] + bi + bh ----------------
__global__ void __launch_bounds__(256) k_gemm(int phase,
        const float* __restrict__ B0, const float* __restrict__ bi0, const float* __restrict__ bh0,
        const float* __restrict__ B1, const float* __restrict__ bi1, const float* __restrict__ bh1) {
    const float* A = phase ? g_x1 : g_x0;
    int dir = blockIdx.z;
    const float* B  = dir ? B1  : B0;
    const float* bi = dir ? bi1 : bi0;
    const float* bh = dir ? bh1 : bh0;
    float* C = g_pre + (size_t)dir * M640 * G4;

    __shared__ __align__(16) float As[16][68];
    __shared__ __align__(16) float Bs[16][68];

    int tid = threadIdx.x;
    int m0 = blockIdx.y * 64, n0 = blockIdx.x * 64;
    int tx = tid & 15, ty = tid >> 4;
    float acc[4][4];
#pragma unroll
    for (int i = 0; i < 4; i++)
#pragma unroll
        for (int j = 0; j < 4; j++) acc[i][j] = 0.f;

    int ml = tid >> 2, kl = (tid & 3) << 2;
    const float* Ag = A + (size_t)(m0 + ml) * DD + kl;
    const float* Bg = B + (size_t)(n0 + ml) * DD + kl;

    for (int k0 = 0; k0 < DD; k0 += 16) {
        float4 av = *(const float4*)(Ag + k0);
        float4 bv = *(const float4*)(Bg + k0);
        As[kl + 0][ml] = av.x; As[kl + 1][ml] = av.y; As[kl + 2][ml] = av.z; As[kl + 3][ml] = av.w;
        Bs[kl + 0][ml] = bv.x; Bs[kl + 1][ml] = bv.y; Bs[kl + 2][ml] = bv.z; Bs[kl + 3][ml] = bv.w;
        __syncthreads();
#pragma unroll
        for (int kk = 0; kk < 16; kk++) {
            float4 a = *(const float4*)&As[kk][ty << 2];
            float4 b = *(const float4*)&Bs[kk][tx << 2];
            float aa[4] = { a.x, a.y, a.z, a.w };
            float bb[4] = { b.x, b.y, b.z, b.w };
#pragma unroll
            for (int i = 0; i < 4; i++)
#pragma unroll
                for (int j = 0; j < 4; j++) acc[i][j] += aa[i] * bb[j];
        }
        __syncthreads();
    }
#pragma unroll
    for (int i = 0; i < 4; i++) {
        int m = m0 + (ty << 2) + i;
        int n = n0 + (tx << 2);
        float4 o;
        o.x = acc[i][0] + bi[n + 0] + bh[n + 0];
        o.y = acc[i][1] + bi[n + 1] + bh[n + 1];
        o.z = acc[i][2] + bi[n + 2] + bh[n + 2];
        o.w = acc[i][3] + bi[n + 3] + bh[n + 3];
        *(float4*)&C[(size_t)m * G4 + n] = o;
    }
}

// ---------------- bidirectional LSTM scan: DSMEM cluster version ----------------
// grid 16 CTAs = 2 clusters of 8 (cluster 0 = fwd, cluster 1 = bwd).
// CTA owns 32 h-units (128 gate rows); 512 threads.
// warp w = h-segment [w*16,w*16+16), lane covers 4 gate rows (rloc=4*lane..+3).
// h exchanged via st.shared::cluster into every peer's double-buffered hsm,
// synced by one release-arrive per CTA on each peer's mbarrier.
__global__ void __cluster_dims__(CLN, 1, 1) __launch_bounds__(512, 1)
k_scan(int phase, const float* __restrict__ whf, const float* __restrict__ whb) {
    extern __shared__ float smf[];
    float* wT   = smf + OFF_W;
    float* hsm  = smf + OFF_H;      // [2][NB][256]
    float* red  = smf + OFF_RED;    // [(w*NB+b)][RPITCH]
    float* garr = smf + OFF_GARR;   // [640] : v = b*128 + rloc
    __shared__ __align__(8) unsigned long long s_mbar;

    float* out = phase ? g_lout : g_x1;
    int dir   = blockIdx.x >> 3;
    int cbase = (blockIdx.x & 7) << 5;     // first h-unit owned by this CTA
    const float* whh  = dir ? whb : whf;
    const float* preb = g_pre + (size_t)dir * M640 * G4;

    int tid = threadIdx.x;
    unsigned mb = smem_u32(&s_mbar);
    if (tid == 0) mbar_init(mb, CLN);

    // load + transpose weights: wT[e*WPITCH + r] = whh[j(r)*HH + e]
    for (int idx = tid; idx < 128 * 64; idx += 512) {
        int r = idx >> 6, e4 = idx & 63;
        int j = ((r >> 5) << 8) + cbase + (r & 31);
        float4 v = *(const float4*)(whh + (size_t)j * HH + (e4 << 2));
        wT[(e4 * 4 + 0) * WPITCH + r] = v.x;
        wT[(e4 * 4 + 1) * WPITCH + r] = v.y;
        wT[(e4 * 4 + 2) * WPITCH + r] = v.z;
        wT[(e4 * 4 + 3) * WPITCH + r] = v.w;
    }
    __syncthreads();
    cluster_sync_();   // mbarriers + smem live in all peers before any remote op

    int w = tid >> 5, lane = tid & 31;
    int rl4 = lane << 2;
    int e0  = w << 4;

    // reduce role: value v = tid (b=v>>7, rloc=v&127); tid<128 also v=512+tid (b=4)
    int b0 = tid >> 7, r0 = tid & 127;
    size_t preoff0 = (size_t)b0 * G4 + ((r0 >> 5) << 8) + cbase + (r0 & 31);
    bool twoV = tid < 128;
    size_t preoff1 = (size_t)4 * G4 + ((tid >> 5) << 8) + cbase + (tid & 31);

    // activation role: a = u*NB + b  (a<160)
    bool isact = tid < 32 * NB;
    int ua = tid / NB, ba = tid - NB * ua;
    int hg = cbase + ua;
    size_t outoff = (size_t)ba * DD + (size_t)dir * HH + hg;
    unsigned smb = smem_u32(smf);
    unsigned ha0 = smb + 4u * (OFF_H + 0    + ba * 256 + hg);
    unsigned ha1 = smb + 4u * (OFF_H + 1280 + ba * 256 + hg);

    float cstate = 0.f;

    for (int s = 0; s < NT; s++) {
        int t = dir ? (NT - 1 - s) : s;

        // prefetch pre-gates (overlap with matvec)
        float pre0 = __ldg(preb + (size_t)t * (NB * G4) + preoff0);
        float pre1 = twoV ? __ldg(preb + (size_t)t * (NB * G4) + preoff1) : 0.f;

        float2 accL[NB], accH[NB];
#pragma unroll
        for (int b = 0; b < NB; b++) { accL[b] = make_float2(0.f, 0.f); accH[b] = make_float2(0.f, 0.f); }

        if (s > 0) {
            const float* hp = hsm + ((s - 1) & 1) * (NB * 256);
#pragma unroll
            for (int e4 = 0; e4 < 4; e4++) {
                int ee = e0 + (e4 << 2);
                float4 w0 = *(const float4*)(wT + (ee + 0) * WPITCH + rl4);
                float4 w1 = *(const float4*)(wT + (ee + 1) * WPITCH + rl4);
                float4 w2 = *(const float4*)(wT + (ee + 2) * WPITCH + rl4);
                float4 w3 = *(const float4*)(wT + (ee + 3) * WPITCH + rl4);
#pragma unroll
                for (int b = 0; b < NB; b++) {
                    float4 h = *(const float4*)(hp + b * 256 + ee);   // broadcast
                    accL[b] = f2fma(make_float2(w0.x, w0.y), make_float2(h.x, h.x), accL[b]);
                    accH[b] = f2fma(make_float2(w0.z, w0.w), make_float2(h.x, h.x), accH[b]);
                    accL[b] = f2fma(make_float2(w1.x, w1.y), make_float2(h.y, h.y), accL[b]);
                    accH[b] = f2fma(make_float2(w1.z, w1.w), make_float2(h.y, h.y), accH[b]);
                    accL[b] = f2fma(make_float2(w2.x, w2.y), make_float2(h.z, h.z), accL[b]);
                    accH[b] = f2fma(make_float2(w2.z, w2.w), make_float2(h.z, h.z), accH[b]);
                    accL[b] = f2fma(make_float2(w3.x, w3.y), make_float2(h.w, h.w), accL[b]);
                    accH[b] = f2fma(make_float2(w3.z, w3.w), make_float2(h.w, h.w), accH[b]);
                }
            }
        }
#pragma unroll
        for (int b = 0; b < NB; b++)
            *(float4*)(red + (w * NB + b) * RPITCH + rl4) =
                make_float4(accL[b].x, accL[b].y, accH[b].x, accH[b].y);
        __syncthreads();

        {
            float s0 = pre0;
#pragma unroll
            for (int ww = 0; ww < 16; ww++) s0 += red[(ww * NB + b0) * RPITCH + r0];
            garr[tid] = s0;
            if (twoV) {
                float s1 = pre1;
#pragma unroll
                for (int ww = 0; ww < 16; ww++) s1 += red[(ww * NB + 4) * RPITCH + tid];
                garr[512 + tid] = s1;
            }
        }
        __syncthreads();

        if (isact) {
            float ig = garr[ba * 128 + ua];
            float fg = garr[ba * 128 + 32 + ua];
            float cg = garr[ba * 128 + 64 + ua];
            float og = garr[ba * 128 + 96 + ua];
            float si = fast_sigmoid(ig);
            float sf = fast_sigmoid(fg);
            float so = fast_sigmoid(og);
            cstate = sf * cstate + si * fast_tanh(cg);
            float hv = so * fast_tanh(cstate);
            out[(size_t)t * (NB * DD) + outoff] = hv;
            if (s < NT - 1) {
                unsigned ha = (s & 1) ? ha1 : ha0;
#pragma unroll
                for (int p = 0; p < CLN; p++) st_cluster(ha, (unsigned)p, hv);
            }
        }
        __syncthreads();

        if (s == NT - 1) break;

        if (tid == 0) {
#pragma unroll
            for (int p = 0; p < CLN; p++) arrive_cluster(mb, (unsigned)p);
        }
        wait_parity_cluster(mb, (unsigned)(s & 1));
    }
    cluster_sync_();   // no CTA exits while peers might still be mid-step
}

// ---------------- attention + softmax + context ----------------
__global__ void k_attn(const float* __restrict__ cs, float* __restrict__ outp) {
    __shared__ __align__(16) float css[DD];
    __shared__ float aw[NT];
    __shared__ float r1[NT];
    int b = blockIdx.x, tid = threadIdx.x;
    ((float4*)css)[tid] = ((const float4*)cs)[tid];
    __syncthreads();

    const float4* lb = (const float4*)(g_lout + ((size_t)tid * NB + b) * DD);
    float att = 0.f;
#pragma unroll 4
    for (int i = 0; i < DD / 4; i++) {
        float4 x = lb[i];
        float4 c = ((float4*)css)[i];
        att += x.x * c.x + x.y * c.y + x.z * c.z + x.w * c.w;
    }
    r1[tid] = att;
    __syncthreads();
    for (int st = 64; st > 0; st >>= 1) {
        if (tid < st) r1[tid] = fmaxf(r1[tid], r1[tid + st]);
        __syncthreads();
    }
    float mx = r1[0];
    __syncthreads();
    float e = expf(att - mx);
    r1[tid] = e;
    __syncthreads();
    for (int st = 64; st > 0; st >>= 1) {
        if (tid < st) r1[tid] += r1[tid + st];
        __syncthreads();
    }
    float inv = 1.f / r1[0];
    __syncthreads();
    aw[tid] = e * inv;
    __syncthreads();

    float4 ctx = make_float4(0.f, 0.f, 0.f, 0.f);
    for (int l = 0; l < NT; l++) {
        float wv = aw[l];
        float4 x = *(const float4*)(g_lout + ((size_t)l * NB + b) * DD + (tid << 2));
        ctx.x += wv * x.x; ctx.y += wv * x.y; ctx.z += wv * x.z; ctx.w += wv * x.w;
    }
    *(float4*)(outp + (size_t)b * DD + (tid << 2)) = ctx;
}

// ---------------- launcher ----------------
extern "C" void kernel_launch(void* const* d_in, const int* in_sizes, int n_in,
                              void* d_out, int out_size) {
    const float* episodes = (const float*)d_in[0];
    const float* query    = (const float*)d_in[1];
    const float* cstate   = (const float*)d_in[2];
    const float* ages     = (const float*)d_in[3];
    const float* Wq = (const float*)d_in[4];
    const float* bq = (const float*)d_in[5];
    const float* Wk = (const float*)d_in[6];
    const float* bk = (const float*)d_in[7];
    const float* w_ih_l0  = (const float*)d_in[8];
    const float* w_hh_l0  = (const float*)d_in[9];
    const float* b_ih_l0  = (const float*)d_in[10];
    const float* b_hh_l0  = (const float*)d_in[11];
    const float* w_ih_l0r = (const float*)d_in[12];
    const float* w_hh_l0r = (const float*)d_in[13];
    const float* b_ih_l0r = (const float*)d_in[14];
    const float* b_hh_l0r = (const float*)d_in[15];
    const float* w_ih_l1  = (const float*)d_in[16];
    const float* w_hh_l1  = (const float*)d_in[17];
    const float* b_ih_l1  = (const float*)d_in[18];
    const float* b_hh_l1  = (const float*)d_in[19];
    const float* w_ih_l1r = (const float*)d_in[20];
    const float* w_hh_l1r = (const float*)d_in[21];
    const float* b_ih_l1r = (const float*)d_in[22];
    const float* b_hh_l1r = (const float*)d_in[23];
    float* out = (float*)d_out;

    // opt-in smem for the scan kernel (idempotent; not a stream op)
    static int smem_set = 0;
    if (!smem_set) {
        cudaFuncSetAttribute(k_scan, cudaFuncAttributeMaxDynamicSharedMemorySize,
                             SMEM_SCAN_BYTES);
        smem_set = 1;
    }

    k_prep  <<<1, 512>>>(query, Wq, bq, Wk, bk);
    k_scores<<<NEP, 256>>>(episodes);
    k_topk  <<<1, 1024>>>(ages);
    k_gather<<<dim3(NT, NB), 128>>>(episodes);

    k_gemm<<<dim3(16, 10, 2), 256>>>(0, w_ih_l0, b_ih_l0, b_hh_l0,
                                        w_ih_l0r, b_ih_l0r, b_hh_l0r);
    k_scan<<<2 * CLN, 512, SMEM_SCAN_BYTES>>>(0, w_hh_l0, w_hh_l0r);

    k_gemm<<<dim3(16, 10, 2), 256>>>(1, w_ih_l1, b_ih_l1, b_hh_l1,
                                        w_ih_l1r, b_ih_l1r, b_hh_l1r);
    k_scan<<<2 * CLN, 512, SMEM_SCAN_BYTES>>>(1, w_hh_l1, w_hh_l1r);

    k_attn<<<NB, 128>>>(cstate, out);
}

// round 11
// speedup vs baseline: 1.2594x; 1.2594x over previous
#include <cuda_runtime.h>
#include <math.h>

#define DD    512
#define HH    256
#define G4    1024
#define NT    128
#define NB    5
#define NEP   1024
#define M640  640      // NT*NB
#define CLN   8        // cluster size (CTAs per direction)

// ---------- static device scratch (no allocation) ----------
__device__ __align__(16) float g_v[DD];
__device__ float g_c0;
__device__ __align__(16) float g_scores[NEP];
__device__ int   g_idx[8];
__device__ float g_wsel[8];
__device__ __align__(16) float g_x0 [M640 * DD];
__device__ __align__(16) float g_x1 [M640 * DD];
__device__ __align__(16) float g_lout[M640 * DD];
__device__ __align__(16) float g_pre[2 * M640 * G4];

// ---------- helpers ----------
union F2U { float2 f; unsigned long long u; };
__device__ __forceinline__ float2 f2fma(float2 a, float2 b, float2 c) {
    F2U A, B, C, Dv; A.f = a; B.f = b; C.f = c;
    asm("fma.rn.f32x2 %0, %1, %2, %3;" : "=l"(Dv.u) : "l"(A.u), "l"(B.u), "l"(C.u));
    return Dv.f;
}
__device__ __forceinline__ float fast_tanh(float x) {
    float r; asm("tanh.approx.f32 %0, %1;" : "=f"(r) : "f"(x)); return r;
}
__device__ __forceinline__ float fast_sigmoid(float x) {
    return __fdividef(1.f, 1.f + __expf(-x));
}
__device__ __forceinline__ unsigned smem_u32(const void* p) {
    return (unsigned)__cvta_generic_to_shared(p);
}
__device__ __forceinline__ void mbar_init(unsigned a, unsigned cnt) {
    asm volatile("mbarrier.init.shared.b64 [%0], %1;" :: "r"(a), "r"(cnt) : "memory");
}
__device__ __forceinline__ void cluster_sync_() {
    asm volatile("barrier.cluster.arrive.aligned;" ::: "memory");
    asm volatile("barrier.cluster.wait.aligned;" ::: "memory");
}
__device__ __forceinline__ void st_cluster(unsigned laddr, unsigned rank, float v) {
    asm volatile("{\n\t.reg .b32 ra;\n\t"
                 "mapa.shared::cluster.u32 ra, %0, %1;\n\t"
                 "st.shared::cluster.f32 [ra], %2;\n\t}"
                 :: "r"(laddr), "r"(rank), "f"(v) : "memory");
}
__device__ __forceinline__ void arrive_cluster(unsigned mbar, unsigned rank) {
    asm volatile("{\n\t.reg .b32 ra;\n\t"
                 "mapa.shared::cluster.u32 ra, %0, %1;\n\t"
                 "mbarrier.arrive.release.cluster.shared::cluster.b64 _, [ra];\n\t}"
                 :: "r"(mbar), "r"(rank) : "memory");
}
__device__ __forceinline__ void wait_parity_cluster(unsigned mbar, unsigned parity) {
    asm volatile(
        "{\n\t.reg .pred P;\n"
        "LAB_%=:\n\t"
        "mbarrier.try_wait.parity.acquire.cluster.shared::cta.b64 P, [%0], %1, 0x989680;\n\t"
        "@P bra.uni DONE_%=;\n\t"
        "bra.uni LAB_%=;\n"
        "DONE_%=:\n\t}"
        :: "r"(mbar), "r"(parity) : "memory");
}

// ---------------- qp = Wq@q + bq ; v = Wk^T@qp ; c0 = bk.qp ----------------
__global__ void k_prep(const float* __restrict__ query, const float* __restrict__ Wq,
                       const float* __restrict__ bq, const float* __restrict__ Wk,
                       const float* __restrict__ bk) {
    __shared__ float qs[DD], qps[DD], red[DD];
    int tid = threadIdx.x;
    qs[tid] = query[tid];
    __syncthreads();
    const float* wr = Wq + (size_t)tid * DD;
    float s = bq[tid];
#pragma unroll 8
    for (int d = 0; d < DD; d++) s += wr[d] * qs[d];
    qps[tid] = s;
    __syncthreads();
    float vv = 0.f;
#pragma unroll 8
    for (int e = 0; e < DD; e++) vv += Wk[(size_t)e * DD + tid] * qps[e];
    g_v[tid] = vv;
    red[tid] = bk[tid] * qps[tid];
    __syncthreads();
    for (int st = 256; st > 0; st >>= 1) {
        if (tid < st) red[tid] += red[tid + st];
        __syncthreads();
    }
    if (tid == 0) g_c0 = red[0];
}

// ---------------- scores[n] = mean_l(ep[n][l]) . v + c0 ----------------
__global__ void k_scores(const float* __restrict__ ep) {
    __shared__ float4 vs[DD / 4];
    __shared__ float sred[256];
    int tid = threadIdx.x;
    if (tid < 128) vs[tid] = ((const float4*)g_v)[tid];
    __syncthreads();
    const float4* e4 = (const float4*)ep + (size_t)blockIdx.x * (NT * DD / 4);
    float acc = 0.f;
#pragma unroll 4
    for (int it = 0; it < 64; it++) {
        int i = tid + 256 * it;
        float4 x = e4[i];
        float4 w = vs[i & 127];
        acc += x.x * w.x + x.y * w.y + x.z * w.z + x.w * w.w;
    }
    sred[tid] = acc;
    __syncthreads();
    for (int st = 128; st > 0; st >>= 1) {
        if (tid < st) sred[tid] += sred[tid + st];
        __syncthreads();
    }
    if (tid == 0) g_scores[blockIdx.x] = sred[0] * (1.0f / NT) + g_c0;
}

// ---------------- iterative top-5 (shuffle argmax) ----------------
__global__ void __launch_bounds__(1024) k_topk(const float* __restrict__ ages) {
    __shared__ float sc[NEP];
    __shared__ float wv_[32];
    __shared__ int   wi_[32];
    int tid = threadIdx.x, lane = tid & 31, wid = tid >> 5;
    sc[tid] = g_scores[tid];
    __syncthreads();
    for (int r = 0; r < NB; r++) {
        float bv = sc[tid]; int bi = tid;
#pragma unroll
        for (int off = 16; off; off >>= 1) {
            float ov = __shfl_down_sync(0xffffffffu, bv, off);
            int   oi = __shfl_down_sync(0xffffffffu, bi, off);
            if (ov > bv || (ov == bv && oi < bi)) { bv = ov; bi = oi; }
        }
        if (lane == 0) { wv_[wid] = bv; wi_[wid] = bi; }
        __syncthreads();
        if (wid == 0) {
            bv = wv_[lane]; bi = wi_[lane];
#pragma unroll
            for (int off = 16; off; off >>= 1) {
                float ov = __shfl_down_sync(0xffffffffu, bv, off);
                int   oi = __shfl_down_sync(0xffffffffu, bi, off);
                if (ov > bv || (ov == bv && oi < bi)) { bv = ov; bi = oi; }
            }
            if (lane == 0) {
                g_idx[r]  = bi;
                g_wsel[r] = 1.f / (1.f + ages[bi] * 0.01f);
                sc[bi] = -INFINITY;
            }
        }
        __syncthreads();
    }
}

// ---------------- x0[t][b][d] = ep[idx[b]][t][d] * w[b] ----------------
__global__ void k_gather(const float* __restrict__ ep) {
    int t = blockIdx.x, b = blockIdx.y, tid = threadIdx.x;
    int n = g_idx[b];
    float wv = g_wsel[b];
    const float4* src = (const float4*)(ep + ((size_t)n * NT + t) * DD);
    float4* dst = (float4*)(g_x0 + ((size_t)t * NB + b) * DD);
    float4 x = src[tid];
    x.x *= wv; x.y *= wv; x.z *= wv; x.w *= wv;
    dst[tid] = x;
}

// ---------------- pre-gate GEMM (f32x2 FMA): pre = X.Wih^T + bi + bh ----------------
__global__ void __launch_bounds__(256) k_gemm(int phase,
        const float* __restrict__ B0, const float* __restrict__ bi0, const float* __restrict__ bh0,
        const float* __restrict__ B1, const float* __restrict__ bi1, const float* __restrict__ bh1) {
    const float* A = phase ? g_x1 : g_x0;
    int dir = blockIdx.z;
    const float* B  = dir ? B1  : B0;
    const float* bi = dir ? bi1 : bi0;
    const float* bh = dir ? bh1 : bh0;
    float* C = g_pre + (size_t)dir * M640 * G4;

    __shared__ __align__(16) float As[16][68];
    __shared__ __align__(16) float Bs[16][68];

    int tid = threadIdx.x;
    int m0 = blockIdx.y * 64, n0 = blockIdx.x * 64;
    int tx = tid & 15, ty = tid >> 4;
    float2 accL[4], accH[4];
#pragma unroll
    for (int i = 0; i < 4; i++) { accL[i] = make_float2(0.f, 0.f); accH[i] = make_float2(0.f, 0.f); }

    int ml = tid >> 2, kl = (tid & 3) << 2;
    const float* Ag = A + (size_t)(m0 + ml) * DD + kl;
    const float* Bg = B + (size_t)(n0 + ml) * DD + kl;

    for (int k0 = 0; k0 < DD; k0 += 16) {
        float4 av = *(const float4*)(Ag + k0);
        float4 bv = *(const float4*)(Bg + k0);
        As[kl + 0][ml] = av.x; As[kl + 1][ml] = av.y; As[kl + 2][ml] = av.z; As[kl + 3][ml] = av.w;
        Bs[kl + 0][ml] = bv.x; Bs[kl + 1][ml] = bv.y; Bs[kl + 2][ml] = bv.z; Bs[kl + 3][ml] = bv.w;
        __syncthreads();
#pragma unroll
        for (int kk = 0; kk < 16; kk++) {
            float4 a = *(const float4*)&As[kk][ty << 2];
            float4 b = *(const float4*)&Bs[kk][tx << 2];
            float2 b01 = make_float2(b.x, b.y), b23 = make_float2(b.z, b.w);
            float aa[4] = { a.x, a.y, a.z, a.w };
#pragma unroll
            for (int i = 0; i < 4; i++) {
                float2 ad = make_float2(aa[i], aa[i]);
                accL[i] = f2fma(ad, b01, accL[i]);
                accH[i] = f2fma(ad, b23, accH[i]);
            }
        }
        __syncthreads();
    }
#pragma unroll
    for (int i = 0; i < 4; i++) {
        int m = m0 + (ty << 2) + i;
        int n = n0 + (tx << 2);
        float4 o;
        o.x = accL[i].x + bi[n + 0] + bh[n + 0];
        o.y = accL[i].y + bi[n + 1] + bh[n + 1];
        o.z = accH[i].x + bi[n + 2] + bh[n + 2];
        o.w = accH[i].y + bi[n + 3] + bh[n + 3];
        *(float4*)&C[(size_t)m * G4 + n] = o;
    }
}

// ---------------- bidirectional LSTM scan: DSMEM cluster, w_hh in registers ----------------
// grid 16 = 2 clusters of 8 (fwd / bwd). 512 threads/CTA, CTA owns 32 h-units
// (128 gate rows). Warp = (gate = w>>2, h-seg = w&3 of 64); lane = unit.
// Each thread holds 64 w_hh floats in registers. h exchanged via
// st.shared::cluster into every peer's double-buffered hsm; synced by one
// parallel release-arrive per peer (lanes 0..7) on each peer's mbarrier.
__global__ void __cluster_dims__(CLN, 1, 1) __launch_bounds__(512, 1)
k_scan(int phase, const float* __restrict__ whf, const float* __restrict__ whb) {
    __shared__ __align__(16) float hsm[2][NB][HH];   // 2.5 K floats
    __shared__ float red[4][128][NB];                // seg partials
    __shared__ float garr[640];                      // gate pre-acts, v = rloc*5+b
    __shared__ __align__(8) unsigned long long s_mbar;

    float* out = phase ? g_lout : g_x1;
    int dir   = blockIdx.x >> 3;
    int cbase = (blockIdx.x & 7) << 5;               // first h-unit owned
    const float* whh  = dir ? whb : whf;
    const float* preb = g_pre + (size_t)dir * M640 * G4;

    int tid = threadIdx.x;
    int lane = tid & 31, warp = tid >> 5;
    int sseg = warp & 3;          // h segment [sseg*64, +64)
    int gate = warp >> 2;         // 0..3
    unsigned mb = smem_u32(&s_mbar);
    if (tid == 0) mbar_init(mb, CLN);

    // w_hh slice into registers: row j, h elems [sseg*64, sseg*64+64)
    float4 wreg[16];
    {
        int j = gate * HH + cbase + lane;
        const float4* wp = (const float4*)(whh + (size_t)j * HH + sseg * 64);
#pragma unroll
        for (int i = 0; i < 16; i++) wreg[i] = wp[i];
    }
    cluster_sync_();   // mbarriers live in all peers before any remote op

    // reduce roles: v0 = tid, v1 = 512+tid (tid<128)
    int rl0 = tid / NB,         b0 = tid - rl0 * NB;
    int rl1 = (512 + tid) / NB, b1 = (512 + tid) - rl1 * NB;
    size_t preoff0 = (size_t)b0 * G4 + (rl0 >> 5) * HH + cbase + (rl0 & 31);
    size_t preoff1 = (size_t)b1 * G4 + (rl1 >> 5) * HH + cbase + (rl1 & 31);
    bool twoV = tid < 128;

    // activation role: tid < 160 -> (unit ua, batch ba)
    bool isact = tid < 32 * NB;
    int ua = tid / NB, ba = tid - NB * ua;
    int hg = cbase + ua;
    size_t outoff = (size_t)ba * DD + (size_t)dir * HH + hg;
    unsigned ha0 = smem_u32(&hsm[0][0][0]) + 4u * (ba * HH + hg);
    unsigned ha1 = ha0 + 4u * (NB * HH);
    float cstate = 0.f;

    for (int s = 0; s < NT; s++) {
        int t = dir ? (NT - 1 - s) : s;

        // prefetch pre-gates (independent of h; overlaps matvec)
        size_t pbase = (size_t)t * (NB * G4);
        float pre0 = __ldg(preb + pbase + preoff0);
        float pre1 = twoV ? __ldg(preb + pbase + preoff1) : 0.f;

        float2 acc[NB];
#pragma unroll
        for (int b = 0; b < NB; b++) acc[b] = make_float2(0.f, 0.f);
        if (s > 0) {
            const float* hp = &hsm[(s - 1) & 1][0][0];
            int ebase = sseg * 64;
#pragma unroll
            for (int e4 = 0; e4 < 16; e4++) {
                float4 wv = wreg[e4];
                float2 w01 = make_float2(wv.x, wv.y), w23 = make_float2(wv.z, wv.w);
                int ee = ebase + (e4 << 2);
#pragma unroll
                for (int b = 0; b < NB; b++) {
                    float4 h = *(const float4*)(hp + b * HH + ee);   // broadcast
                    acc[b] = f2fma(w01, make_float2(h.x, h.y), acc[b]);
                    acc[b] = f2fma(w23, make_float2(h.z, h.w), acc[b]);
                }
            }
        }
        {
            int rloc = (gate << 5) + lane;
#pragma unroll
            for (int b = 0; b < NB; b++) red[sseg][rloc][b] = acc[b].x + acc[b].y;
        }
        __syncthreads();

        // reduce 4 seg partials + pre-gate
        {
            float s0 = pre0 + red[0][rl0][b0] + red[1][rl0][b0]
                            + red[2][rl0][b0] + red[3][rl0][b0];
            garr[tid] = s0;
            if (twoV) {
                float s1 = pre1 + red[0][rl1][b1] + red[1][rl1][b1]
                                + red[2][rl1][b1] + red[3][rl1][b1];
                garr[512 + tid] = s1;
            }
        }
        __syncthreads();

        if (isact) {
            float ig = garr[(ua)          * NB + ba];
            float fg = garr[(32 + ua) * NB + ba];
            float cg = garr[(64 + ua) * NB + ba];
            float og = garr[(96 + ua) * NB + ba];
            float si = fast_sigmoid(ig);
            float sf = fast_sigmoid(fg);
            float so = fast_sigmoid(og);
            cstate = sf * cstate + si * fast_tanh(cg);
            float hv = so * fast_tanh(cstate);
            out[(size_t)t * (NB * DD) + outoff] = hv;
            if (s < NT - 1) {
                unsigned ha = (s & 1) ? ha1 : ha0;
#pragma unroll
                for (int p = 0; p < CLN; p++) st_cluster(ha, (unsigned)p, hv);
            }
        }
        __syncthreads();

        if (s == NT - 1) break;

        if (tid < CLN) arrive_cluster(mb, (unsigned)tid);   // parallel arrives
        wait_parity_cluster(mb, (unsigned)(s & 1));
    }
    cluster_sync_();   // no CTA exits while peers may still reference its smem
}

// ---------------- attention + softmax + context ----------------
__global__ void k_attn(const float* __restrict__ cs, float* __restrict__ outp) {
    __shared__ __align__(16) float css[DD];
    __shared__ float aw[NT];
    __shared__ float r1[NT];
    int b = blockIdx.x, tid = threadIdx.x;
    ((float4*)css)[tid] = ((const float4*)cs)[tid];
    __syncthreads();

    const float4* lb = (const float4*)(g_lout + ((size_t)tid * NB + b) * DD);
    float att = 0.f;
#pragma unroll 4
    for (int i = 0; i < DD / 4; i++) {
        float4 x = lb[i];
        float4 c = ((float4*)css)[i];
        att += x.x * c.x + x.y * c.y + x.z * c.z + x.w * c.w;
    }
    r1[tid] = att;
    __syncthreads();
    for (int st = 64; st > 0; st >>= 1) {
        if (tid < st) r1[tid] = fmaxf(r1[tid], r1[tid + st]);
        __syncthreads();
    }
    float mx = r1[0];
    __syncthreads();
    float e = expf(att - mx);
    r1[tid] = e;
    __syncthreads();
    for (int st = 64; st > 0; st >>= 1) {
        if (tid < st) r1[tid] += r1[tid + st];
        __syncthreads();
    }
    float inv = 1.f / r1[0];
    __syncthreads();
    aw[tid] = e * inv;
    __syncthreads();

    float4 ctx = make_float4(0.f, 0.f, 0.f, 0.f);
    for (int l = 0; l < NT; l++) {
        float wv = aw[l];
        float4 x = *(const float4*)(g_lout + ((size_t)l * NB + b) * DD + (tid << 2));
        ctx.x += wv * x.x; ctx.y += wv * x.y; ctx.z += wv * x.z; ctx.w += wv * x.w;
    }
    *(float4*)(outp + (size_t)b * DD + (tid << 2)) = ctx;
}

// ---------------- launcher ----------------
extern "C" void kernel_launch(void* const* d_in, const int* in_sizes, int n_in,
                              void* d_out, int out_size) {
    const float* episodes = (const float*)d_in[0];
    const float* query    = (const float*)d_in[1];
    const float* cstate   = (const float*)d_in[2];
    const float* ages     = (const float*)d_in[3];
    const float* Wq = (const float*)d_in[4];
    const float* bq = (const float*)d_in[5];
    const float* Wk = (const float*)d_in[6];
    const float* bk = (const float*)d_in[7];
    const float* w_ih_l0  = (const float*)d_in[8];
    const float* w_hh_l0  = (const float*)d_in[9];
    const float* b_ih_l0  = (const float*)d_in[10];
    const float* b_hh_l0  = (const float*)d_in[11];
    const float* w_ih_l0r = (const float*)d_in[12];
    const float* w_hh_l0r = (const float*)d_in[13];
    const float* b_ih_l0r = (const float*)d_in[14];
    const float* b_hh_l0r = (const float*)d_in[15];
    const float* w_ih_l1  = (const float*)d_in[16];
    const float* w_hh_l1  = (const float*)d_in[17];
    const float* b_ih_l1  = (const float*)d_in[18];
    const float* b_hh_l1  = (const float*)d_in[19];
    const float* w_ih_l1r = (const float*)d_in[20];
    const float* w_hh_l1r = (const float*)d_in[21];
    const float* b_ih_l1r = (const float*)d_in[22];
    const float* b_hh_l1r = (const float*)d_in[23];
    float* out = (float*)d_out;

    k_prep  <<<1, 512>>>(query, Wq, bq, Wk, bk);
    k_scores<<<NEP, 256>>>(episodes);
    k_topk  <<<1, 1024>>>(ages);
    k_gather<<<dim3(NT, NB), 128>>>(episodes);

    k_gemm<<<dim3(16, 10, 2), 256>>>(0, w_ih_l0, b_ih_l0, b_hh_l0,
                                        w_ih_l0r, b_ih_l0r, b_hh_l0r);
    k_scan<<<2 * CLN, 512>>>(0, w_hh_l0, w_hh_l0r);

    k_gemm<<<dim3(16, 10, 2), 256>>>(1, w_ih_l1, b_ih_l1, b_hh_l1,
                                        w_ih_l1r, b_ih_l1r, b_hh_l1r);
    k_scan<<<2 * CLN, 512>>>(1, w_hh_l1, w_hh_l1r);

    k_attn<<<NB, 128>>>(cstate, out);
}